// round 3
// baseline (speedup 1.0000x reference)
#include <cuda_runtime.h>
#include <math.h>

#define D_    1024
#define E_    8
#define B_    64
#define S_    1024
#define NTOK  65536
#define NB2   2048                 // K2 blocks: 32 tokens each, batch-aligned
#define MASK_N   (B_*S_*E_)        // 524288
#define IDX_OFF  MASK_N
#define LOSS_OFF (MASK_N + B_*2)   // 524416
#define SCALE 0.03125f             // D^-0.5

typedef unsigned long long u64;

// ----- static scratch (no allocation) -----
__device__ float g_Mpart[16*8192];   // 512 KB: o-tile partials of M, [tile][e*1024+d]
__device__ float g_M[8192];          // M[e][d]
__device__ float g_c[8];
__device__ float g_pws[NB2*8];       // per-block softmax sums per expert
__device__ float g_paux[NB2];        // per-block aux partial
__device__ float g_m2d[64*8];        // mask2d

__device__ __forceinline__ void ffma2(u64 &d, u64 a, u64 b){
    asm("fma.rn.f32x2 %0, %1, %2, %0;" : "+l"(d) : "l"(a), "l"(b));
}
__device__ __forceinline__ float2 unpack2(u64 v){
    float2 r; asm("mov.b64 {%0,%1}, %2;" : "=f"(r.x), "=f"(r.y) : "l"(v)); return r;
}
union F4u { float4 f; u64 u[2]; };

// ================= K1: partial M[d,e] = sum_o Wq[o,d]*key[e,o] over o-tile =================
__global__ void k1(const float* __restrict__ Wq, const float* __restrict__ key){
    __shared__ float sk[512];                  // key[e][o-tile], 8 x 64
    int tid = threadIdx.x;
    int ot = blockIdx.x & 15, dt = blockIdx.x >> 4;
    int o0 = ot << 6;
    for (int i = tid; i < 512; i += 256){
        int e = i >> 6, oo = i & 63;
        sk[i] = key[(e<<10) + o0 + oo];
    }
    __syncthreads();
    int d = (dt<<8) + tid;
    float acc[8] = {0.f,0.f,0.f,0.f,0.f,0.f,0.f,0.f};
    #pragma unroll 4
    for (int oo = 0; oo < 64; oo++){
        float w = Wq[(size_t)(o0+oo)*D_ + d];  // coalesced in d
        #pragma unroll
        for (int e = 0; e < 8; e++) acc[e] = fmaf(w, sk[(e<<6)+oo], acc[e]);
    }
    #pragma unroll
    for (int e = 0; e < 8; e++)
        g_Mpart[ot*8192 + (e<<10) + d] = acc[e];
}

// ================= K1b: reduce 16 partials -> g_M; compute c[e] = key[e]·bq =================
__global__ void k1b(const float* __restrict__ key, const float* __restrict__ bq){
    int i = blockIdx.x*256 + threadIdx.x;      // 0..8191  (= e*1024+d)
    float t = 0.f;
    #pragma unroll
    for (int k = 0; k < 16; k++) t += g_Mpart[k*8192 + i];
    g_M[i] = t;

    if (blockIdx.x == 0){
        int e = threadIdx.x >> 5, lane = threadIdx.x & 31;
        float c = 0.f;
        for (int o = lane; o < D_; o += 32) c = fmaf(key[(e<<10)+o], bq[o], c);
        #pragma unroll
        for (int off = 16; off > 0; off >>= 1)
            c += __shfl_xor_sync(0xffffffffu, c, off);
        if (lane == 0) g_c[e] = c;
    }
}

// ================= K2: fused projection + softmax + per-block partial sums =================
// 256 threads = 8 warps; each warp handles 4 tokens with 8 lanes per token.
// Lane layout: g = lane>>3 (token-in-warp), s8 = lane&7 (d-subchunk).
__global__ void __launch_bounds__(256) k2(const float* __restrict__ x){
    __shared__ float sM[8*1024];    // 32 KB, [e][d]
    __shared__ float sC[8];
    __shared__ float sRed[8][12];
    int tid = threadIdx.x;

    const float4* gM4 = (const float4*)g_M;
    float4* sM4 = (float4*)sM;
    #pragma unroll
    for (int i = 0; i < 8; i++) sM4[i*256 + tid] = gM4[i*256 + tid];
    if (tid < 8) sC[tid] = g_c[tid];
    __syncthreads();

    int lane = tid & 31, warp = tid >> 5;
    int g = lane >> 3, s8 = lane & 7;
    int token = blockIdx.x*32 + warp*4 + g;
    const float4* xr = (const float4*)(x + (size_t)token*D_);

    u64 acc[8];
    #pragma unroll
    for (int e = 0; e < 8; e++) acc[e] = 0ULL;

    // Each chunk covers 32 d's: 8 lanes x float4. Warp's x LDG.128 = 4 rows x 128B (4 lines).
    // M LDS.128: 8 consecutive 16B addrs (128B, conflict-free), multicast to 4 token groups.
    #pragma unroll 4
    for (int ch = 0; ch < 32; ch++){
        F4u xv; xv.f = xr[ch*8 + s8];
        int db = (ch<<5) + (s8<<2);
        #pragma unroll
        for (int e = 0; e < 8; e++){
            ulonglong2 mv = *(const ulonglong2*)(sM + (e<<10) + db);
            ffma2(acc[e], xv.u[0], mv.x);
            ffma2(acc[e], xv.u[1], mv.y);
        }
    }

    // collapse pairs + reduce over the 8 lanes of this token
    float s[8];
    #pragma unroll
    for (int e = 0; e < 8; e++){
        float2 p = unpack2(acc[e]);
        float v = p.x + p.y;
        #pragma unroll
        for (int off = 1; off < 8; off <<= 1)
            v += __shfl_xor_sync(0xffffffffu, v, off);
        s[e] = (v + sC[e]) * SCALE;
    }

    // softmax (all 8 lanes of a token hold identical s[] -> redundant but cheap)
    float mx = s[0];
    #pragma unroll
    for (int e = 1; e < 8; e++) mx = fmaxf(mx, s[e]);
    float w[8], sum = 0.f;
    #pragma unroll
    for (int e = 0; e < 8; e++){ w[e] = __expf(s[e] - mx); sum += w[e]; }
    float inv = 1.0f / sum;
    float aux = 0.f;
    #pragma unroll
    for (int e = 0; e < 8; e++){ w[e] *= inv; aux += w[e] * __logf(w[e] + 1e-9f); }

    // count each token once: zero non-lead lanes, then full-warp butterfly
    float lead = (s8 == 0) ? 1.f : 0.f;
    aux *= lead;
    #pragma unroll
    for (int e = 0; e < 8; e++) w[e] *= lead;
    #pragma unroll
    for (int off = 16; off > 0; off >>= 1){
        #pragma unroll
        for (int e = 0; e < 8; e++) w[e] += __shfl_xor_sync(0xffffffffu, w[e], off);
        aux += __shfl_xor_sync(0xffffffffu, aux, off);
    }
    if (lane == 0){
        #pragma unroll
        for (int e = 0; e < 8; e++) sRed[warp][e] = w[e];
        sRed[warp][8] = aux;
    }
    __syncthreads();
    if (tid < 9){
        float t = 0.f;
        #pragma unroll
        for (int wp = 0; wp < 8; wp++) t += sRed[wp][tid];
        if (tid < 8) g_pws[blockIdx.x*8 + tid] = t;
        else         g_paux[blockIdx.x]        = t;
    }
}

// ================= K3: per-batch top-2, mask2d, router loss =================
__global__ void k3(float* __restrict__ out, int out_size){
    __shared__ float sm2[64][8];
    __shared__ float saux[8];
    int tid = threadIdx.x;
    int lane = tid & 31, warp = tid >> 5;

    // aux reduction over 2048 block partials (all 256 threads participate)
    float a = 0.f;
    #pragma unroll
    for (int k = 0; k < 8; k++) a += g_paux[tid + k*256];
    #pragma unroll
    for (int off = 16; off > 0; off >>= 1)
        a += __shfl_xor_sync(0xffffffffu, a, off);
    if (lane == 0) saux[warp] = a;

    if (tid < 64){
        int b = tid;
        float sc[8];
        #pragma unroll
        for (int e = 0; e < 8; e++){
            float t = 0.f;
            for (int j = 0; j < 32; j++) t += g_pws[((b<<5)+j)*8 + e];
            sc[e] = t;   // proportional to scores[b][e]
        }
        // top-2, ties -> lowest index (matches jax.lax.top_k)
        int i1 = 0; float v1 = sc[0];
        #pragma unroll
        for (int e = 1; e < 8; e++) if (sc[e] > v1){ v1 = sc[e]; i1 = e; }
        int i2 = -1; float v2 = -3.0e38f;
        #pragma unroll
        for (int e = 0; e < 8; e++) if (e != i1 && sc[e] > v2){ v2 = sc[e]; i2 = e; }
        #pragma unroll
        for (int e = 0; e < 8; e++){
            float mv = (e == i1 || e == i2) ? 1.f : 0.f;
            sm2[b][e] = mv;
            g_m2d[b*8 + e] = mv;
        }
        if (out_size > IDX_OFF + b*2 + 1){
            out[IDX_OFF + b*2 + 0] = (float)i1;
            out[IDX_OFF + b*2 + 1] = (float)i2;
        }
    }
    __syncthreads();

    if (tid == 0){
        float auxtot = 0.f;
        #pragma unroll
        for (int wp = 0; wp < 8; wp++) auxtot += saux[wp];
        float kl = 0.f;
        const float ip = 0.125f;
        const float lip = logf(0.125f);
        #pragma unroll
        for (int e = 0; e < 8; e++){
            float c = 0.f;
            for (int b = 0; b < 64; b++) c += sm2[b][e];
            float usage = c * (1.0f/64.0f);       // mask2d.sum(0) * S/(B*S)
            kl += ip * (lip - logf(usage));
        }
        kl *= 0.125f;                             // batchmean over E
        float auxm = auxtot * (1.0f / (float)(B_*S_*E_));
        if (out_size > LOSS_OFF)
            out[LOSS_OFF] = 1e-3f*kl + 1e-3f*auxm;
    }
}

// ================= K4: broadcast mask2d -> mask[B,S,E] =================
__global__ void k4(float* __restrict__ out){
    int t = blockIdx.x*256 + threadIdx.x;   // 0..65535 (b,s) pairs
    int b = t >> 10;
    const float4* m = (const float4*)g_m2d;
    float4 a0 = m[b*2 + 0];
    float4 a1 = m[b*2 + 1];
    float4* o = (float4*)out;
    o[t*2 + 0] = a0;
    o[t*2 + 1] = a1;
}

extern "C" void kernel_launch(void* const* d_in, const int* in_sizes, int n_in,
                              void* d_out, int out_size){
    (void)in_sizes; (void)n_in;
    const float* x   = (const float*)d_in[0];
    const float* Wq  = (const float*)d_in[1];
    const float* bq  = (const float*)d_in[2];
    const float* key = (const float*)d_in[3];
    float* out = (float*)d_out;

    k1 <<<64,   256>>>(Wq, key);
    k1b<<<32,   256>>>(key, bq);
    k2 <<<NB2,  256>>>(x);
    k3 <<<1,    256>>>(out, out_size);
    k4 <<<256,  256>>>(out);
}

// round 5
// speedup vs baseline: 1.2833x; 1.2833x over previous
#include <cuda_runtime.h>
#include <math.h>

#define D_    1024
#define E_    8
#define B_    64
#define S_    1024
#define NTOK  65536
#define NB2   1024                 // K2 blocks: 64 tokens each, batch-aligned (16 blocks/batch)
#define MASK_N   (B_*S_*E_)        // 524288
#define IDX_OFF  MASK_N
#define LOSS_OFF (MASK_N + B_*2)   // 524416
#define SCALE 0.03125f             // D^-0.5

typedef unsigned long long u64;

// ----- static scratch (no allocation) -----
__device__ float g_Mpart[32*8192];   // 1 MB: o-tile partials of M, [tile][e*1024+d]
__device__ float g_M[8192];          // M[e][d]
__device__ float g_c[8];
__device__ float g_pws[NB2*8];       // per-block softmax sums per expert
__device__ float g_paux[NB2];        // per-block aux partial
__device__ float g_m2d[64*8];        // mask2d

__device__ __forceinline__ void ffma2(u64 &d, u64 a, u64 b){
    asm("fma.rn.f32x2 %0, %1, %2, %0;" : "+l"(d) : "l"(a), "l"(b));
}
__device__ __forceinline__ float2 unpack2(u64 v){
    float2 r; asm("mov.b64 {%0,%1}, %2;" : "=f"(r.x), "=f"(r.y) : "l"(v)); return r;
}
union F4u { float4 f; u64 u[2]; };

// ================= K1: partial M[d,e] = sum_o Wq[o,d]*key[e,o] over 32-wide o-tile =========
// grid 128 = 32 o-tiles x 4 d-tiles; 256 threads each own one d.
__global__ void k1(const float* __restrict__ Wq, const float* __restrict__ key){
    __shared__ float sk[256];                  // key[e][o-tile], 8 x 32
    int tid = threadIdx.x;
    int ot = blockIdx.x & 31, dt = blockIdx.x >> 5;
    int o0 = ot << 5;
    {
        int e = tid >> 5, oo = tid & 31;
        sk[tid] = key[(e<<10) + o0 + oo];
    }
    __syncthreads();
    int d = (dt<<8) + tid;
    float acc[8] = {0.f,0.f,0.f,0.f,0.f,0.f,0.f,0.f};
    #pragma unroll 8
    for (int oo = 0; oo < 32; oo++){
        float w = Wq[(size_t)(o0+oo)*D_ + d];  // coalesced in d
        #pragma unroll
        for (int e = 0; e < 8; e++) acc[e] = fmaf(w, sk[(e<<5)+oo], acc[e]);
    }
    #pragma unroll
    for (int e = 0; e < 8; e++)
        g_Mpart[ot*8192 + (e<<10) + d] = acc[e];
}

// ================= K1b: reduce 32 partials -> g_M; compute c[e] = key[e]·bq =================
__global__ void k1b(const float* __restrict__ key, const float* __restrict__ bq){
    int i = blockIdx.x*256 + threadIdx.x;      // 0..8191  (= e*1024+d)
    float t = 0.f;
    #pragma unroll
    for (int k = 0; k < 32; k++) t += g_Mpart[k*8192 + i];
    g_M[i] = t;

    if (blockIdx.x == 0){
        int e = threadIdx.x >> 5, lane = threadIdx.x & 31;
        float c = 0.f;
        for (int o = lane; o < D_; o += 32) c = fmaf(key[(e<<10)+o], bq[o], c);
        #pragma unroll
        for (int off = 16; off > 0; off >>= 1)
            c += __shfl_xor_sync(0xffffffffu, c, off);
        if (lane == 0) g_c[e] = c;
    }
}

// ================= K2: fused projection + softmax + per-block partial sums =================
// 512 threads = 16 warps; each warp handles 4 tokens with 8 lanes per token.
__global__ void __launch_bounds__(512,2) k2(const float* __restrict__ x){
    __shared__ float sM[8*1024];    // 32 KB, [e][d]
    __shared__ float sC[8];
    __shared__ float sRed[16][12];
    int tid = threadIdx.x;

    const float4* gM4 = (const float4*)g_M;
    float4* sM4 = (float4*)sM;
    #pragma unroll
    for (int i = 0; i < 4; i++) sM4[i*512 + tid] = gM4[i*512 + tid];
    if (tid < 8) sC[tid] = g_c[tid];
    __syncthreads();

    int lane = tid & 31, warp = tid >> 5;
    int g = lane >> 3, s8 = lane & 7;
    int token = blockIdx.x*64 + warp*4 + g;
    const float4* xr = (const float4*)(x + (size_t)token*D_);

    u64 acc[8];
    #pragma unroll
    for (int e = 0; e < 8; e++) acc[e] = 0ULL;

    // Each chunk covers 32 d's: 8 lanes x float4. Warp's x LDG.128 = 4 rows x 128B (4 lines).
    // M LDS.128: 8 consecutive 16B addrs (128B, conflict-free), multicast to 4 token groups.
    #pragma unroll 4
    for (int ch = 0; ch < 32; ch++){
        F4u xv; xv.f = __ldcs(&xr[ch*8 + s8]);   // streamed, no reuse
        int db = (ch<<5) + (s8<<2);
        #pragma unroll
        for (int e = 0; e < 8; e++){
            ulonglong2 mv = *(const ulonglong2*)(sM + (e<<10) + db);
            ffma2(acc[e], xv.u[0], mv.x);
            ffma2(acc[e], xv.u[1], mv.y);
        }
    }

    // collapse pairs + reduce over the 8 lanes of this token
    float s[8];
    #pragma unroll
    for (int e = 0; e < 8; e++){
        float2 p = unpack2(acc[e]);
        float v = p.x + p.y;
        #pragma unroll
        for (int off = 1; off < 8; off <<= 1)
            v += __shfl_xor_sync(0xffffffffu, v, off);
        s[e] = (v + sC[e]) * SCALE;
    }

    // softmax (all 8 lanes of a token hold identical s[] -> redundant but cheap)
    float mx = s[0];
    #pragma unroll
    for (int e = 1; e < 8; e++) mx = fmaxf(mx, s[e]);
    float w[8], sum = 0.f;
    #pragma unroll
    for (int e = 0; e < 8; e++){ w[e] = __expf(s[e] - mx); sum += w[e]; }
    float inv = 1.0f / sum;
    float aux = 0.f;
    #pragma unroll
    for (int e = 0; e < 8; e++){ w[e] *= inv; aux += w[e] * __logf(w[e] + 1e-9f); }

    // count each token once: zero non-lead lanes, then full-warp butterfly
    float lead = (s8 == 0) ? 1.f : 0.f;
    aux *= lead;
    #pragma unroll
    for (int e = 0; e < 8; e++) w[e] *= lead;
    #pragma unroll
    for (int off = 16; off > 0; off >>= 1){
        #pragma unroll
        for (int e = 0; e < 8; e++) w[e] += __shfl_xor_sync(0xffffffffu, w[e], off);
        aux += __shfl_xor_sync(0xffffffffu, aux, off);
    }
    if (lane == 0){
        #pragma unroll
        for (int e = 0; e < 8; e++) sRed[warp][e] = w[e];
        sRed[warp][8] = aux;
    }
    __syncthreads();
    if (tid < 9){
        float t = 0.f;
        #pragma unroll
        for (int wp = 0; wp < 16; wp++) t += sRed[wp][tid];
        if (tid < 8) g_pws[blockIdx.x*8 + tid] = t;
        else         g_paux[blockIdx.x]        = t;
    }
}

// ================= K3: per-batch top-2, mask2d, router loss (512 threads) =================
__global__ void __launch_bounds__(512) k3(float* __restrict__ out, int out_size){
    __shared__ float ssc[64][9];    // scores (padded)
    __shared__ float sm2[64][8];    // mask2d
    __shared__ float sauxw[16];
    __shared__ float scnt[8];
    int tid = threadIdx.x;
    int lane = tid & 31, warp = tid >> 5;

    // aux reduction over 1024 block partials: 2 loads/thread, full MLP
    float a = g_paux[tid] + g_paux[tid + 512];
    #pragma unroll
    for (int off = 16; off > 0; off >>= 1)
        a += __shfl_xor_sync(0xffffffffu, a, off);
    if (lane == 0) sauxw[warp] = a;

    // per-(b,e) score: 16 independent loads, coalesced across e within each 8-thread group
    {
        int b = tid >> 3, e = tid & 7;
        float sc = 0.f;
        #pragma unroll
        for (int j = 0; j < 16; j++) sc += g_pws[((b<<4)+j)*8 + e];
        ssc[b][e] = sc;
    }
    __syncthreads();

    if (tid < 64){
        int b = tid;
        float sc[8];
        #pragma unroll
        for (int e = 0; e < 8; e++) sc[e] = ssc[b][e];
        // top-2, ties -> lowest index (matches jax.lax.top_k)
        int i1 = 0; float v1 = sc[0];
        #pragma unroll
        for (int e = 1; e < 8; e++) if (sc[e] > v1){ v1 = sc[e]; i1 = e; }
        int i2 = -1; float v2 = -3.0e38f;
        #pragma unroll
        for (int e = 0; e < 8; e++) if (e != i1 && sc[e] > v2){ v2 = sc[e]; i2 = e; }
        #pragma unroll
        for (int e = 0; e < 8; e++){
            float mv = (e == i1 || e == i2) ? 1.f : 0.f;
            sm2[b][e] = mv;
            g_m2d[b*8 + e] = mv;
        }
        if (out_size > IDX_OFF + b*2 + 1){
            out[IDX_OFF + b*2 + 0] = (float)i1;
            out[IDX_OFF + b*2 + 1] = (float)i2;
        }
    }
    __syncthreads();

    // per-expert usage counts in parallel
    if (tid < 8){
        float c = 0.f;
        #pragma unroll
        for (int b = 0; b < 64; b++) c += sm2[b][tid];
        scnt[tid] = c;
    }
    __syncthreads();

    if (tid == 0){
        float auxtot = 0.f;
        #pragma unroll
        for (int wp = 0; wp < 16; wp++) auxtot += sauxw[wp];
        float kl = 0.f;
        const float ip = 0.125f;
        const float lip = logf(0.125f);
        #pragma unroll
        for (int e = 0; e < 8; e++){
            float usage = scnt[e] * (1.0f/64.0f);   // mask2d.sum(0) * S/(B*S)
            kl += ip * (lip - logf(usage));
        }
        kl *= 0.125f;                               // batchmean over E
        float auxm = auxtot * (1.0f / (float)(B_*S_*E_));
        if (out_size > LOSS_OFF)
            out[LOSS_OFF] = 1e-3f*kl + 1e-3f*auxm;
    }
}

// ================= K4: broadcast mask2d -> mask[B,S,E] =================
__global__ void k4(float* __restrict__ out){
    int t = blockIdx.x*256 + threadIdx.x;   // 0..65535 (b,s) pairs
    int b = t >> 10;
    const float4* m = (const float4*)g_m2d;
    float4 a0 = m[b*2 + 0];
    float4 a1 = m[b*2 + 1];
    float4* o = (float4*)out;
    o[t*2 + 0] = a0;
    o[t*2 + 1] = a1;
}

extern "C" void kernel_launch(void* const* d_in, const int* in_sizes, int n_in,
                              void* d_out, int out_size){
    (void)in_sizes; (void)n_in;
    const float* x   = (const float*)d_in[0];
    const float* Wq  = (const float*)d_in[1];
    const float* bq  = (const float*)d_in[2];
    const float* key = (const float*)d_in[3];
    float* out = (float*)d_out;

    k1 <<<128,  256>>>(Wq, key);
    k1b<<<32,   256>>>(key, bq);
    k2 <<<NB2,  512>>>(x);
    k3 <<<1,    512>>>(out, out_size);
    k4 <<<256,  256>>>(out);
}